// round 3
// baseline (speedup 1.0000x reference)
#include <cuda_runtime.h>

// StructuredPruningIF: integrate-and-fire over T=4 timesteps.
// Pure streaming (256MB read + 256MB write), HBM-bound at ~81% of spec.
// R3: revert R2's cache hints / MLP-8 (hurt occupancy, no BW gain).
// Persistent grid-stride at exact full occupancy (148 SMs x 8 CTAs) to
// remove wave-transition overhead and tail imbalance.

#define T_STEPS 4

__global__ __launch_bounds__(256) void if_kernel(
    const float4* __restrict__ x,
    const float* __restrict__ thresh,
    float4* __restrict__ out,
    int n4)          // spatial float4 count per timestep (== timestep stride)
{
    const float thre = __ldg(thresh);
    const float half_thre = 0.5f * thre;
    const long s = n4;
    const int step = gridDim.x * blockDim.x;

    for (int i = blockIdx.x * blockDim.x + threadIdx.x; i < n4; i += step) {
        // 4 independent timestep loads in flight (MLP=4 saturates LTS already)
        float4 x0 = x[0 * s + i];
        float4 x1 = x[1 * s + i];
        float4 x2 = x[2 * s + i];
        float4 x3 = x[3 * s + i];

        float4 xts[T_STEPS] = {x0, x1, x2, x3};
        float4 mem = make_float4(half_thre, half_thre, half_thre, half_thre);

#pragma unroll
        for (int t = 0; t < T_STEPS; t++) {
            float4 xt = xts[t];
            float4 spike;

            mem.x += xt.x; spike.x = (mem.x >= thre) ? thre : 0.0f; mem.x -= spike.x;
            mem.y += xt.y; spike.y = (mem.y >= thre) ? thre : 0.0f; mem.y -= spike.y;
            mem.z += xt.z; spike.z = (mem.z >= thre) ? thre : 0.0f; mem.z -= spike.z;
            mem.w += xt.w; spike.w = (mem.w >= thre) ? thre : 0.0f; mem.w -= spike.w;

            out[t * s + i] = spike;
        }
    }
}

extern "C" void kernel_launch(void* const* d_in, const int* in_sizes, int n_in,
                              void* d_out, int out_size) {
    const float* x      = (const float*)d_in[0];   // [512,128,32,32]
    const float* thresh = (const float*)d_in[1];   // [1]
    float* out          = (float*)d_out;

    int total = in_sizes[0];            // 67,108,864
    int per_t = total / T_STEPS;        // 16,777,216
    int n4 = per_t / 4;                 // 4,194,304 float4 lanes

    // Full-occupancy persistent launch: 148 SMs x 8 CTAs of 256 threads
    // (32 regs/thread -> 8 CTAs/SM fits the register file exactly).
    int threads = 256;
    int blocks = 148 * 8;   // 1184
    if_kernel<<<blocks, threads>>>((const float4*)x, thresh, (float4*)out, n4);
}

// round 4
// speedup vs baseline: 1.1361x; 1.1361x over previous
#include <cuda_runtime.h>

// StructuredPruningIF: integrate-and-fire over T=4 timesteps.
// Pure streaming (256MB read + 256MB write), HBM-bound.
// R4: exact R1 structure (best: 74.6us kernel, 6.49TB/s, 32 regs, flat
// one-shot launch, front-batched MLP=4 loads) + __stcs on stores only
// (output never re-read; evict-first frees L2 lines for the read stream).
// R3 post-mortem: persistent grid-stride REGRESSED (MLP drop) - do not reuse.

#define T_STEPS 4

__global__ __launch_bounds__(256) void if_kernel(
    const float4* __restrict__ x,
    const float* __restrict__ thresh,
    float4* __restrict__ out,
    int n4)          // spatial float4 count per timestep (== timestep stride)
{
    int i = blockIdx.x * blockDim.x + threadIdx.x;
    if (i >= n4) return;

    const float thre = __ldg(thresh);
    const long s = n4;

    // Front-batched independent loads (MLP=4) — keep these first in program
    // order; this is what sustains deep L1tex queues across the chip.
    float4 x0 = x[0 * s + i];
    float4 x1 = x[1 * s + i];
    float4 x2 = x[2 * s + i];
    float4 x3 = x[3 * s + i];

    float4 xts[T_STEPS] = {x0, x1, x2, x3};
    float4 mem = make_float4(0.5f * thre, 0.5f * thre, 0.5f * thre, 0.5f * thre);

#pragma unroll
    for (int t = 0; t < T_STEPS; t++) {
        float4 xt = xts[t];
        float4 spike;

        mem.x += xt.x; spike.x = (mem.x >= thre) ? thre : 0.0f; mem.x -= spike.x;
        mem.y += xt.y; spike.y = (mem.y >= thre) ? thre : 0.0f; mem.y -= spike.y;
        mem.z += xt.z; spike.z = (mem.z >= thre) ? thre : 0.0f; mem.z -= spike.z;
        mem.w += xt.w; spike.w = (mem.w >= thre) ? thre : 0.0f; mem.w -= spike.w;

        __stcs(&out[t * s + i], spike);
    }
}

extern "C" void kernel_launch(void* const* d_in, const int* in_sizes, int n_in,
                              void* d_out, int out_size) {
    const float* x      = (const float*)d_in[0];   // [512,128,32,32]
    const float* thresh = (const float*)d_in[1];   // [1]
    float* out          = (float*)d_out;

    int total = in_sizes[0];            // 67,108,864
    int per_t = total / T_STEPS;        // 16,777,216
    int n4 = per_t / 4;                 // 4,194,304 float4 lanes

    int threads = 256;
    int blocks = (n4 + threads - 1) / threads;   // 16384
    if_kernel<<<blocks, threads>>>((const float4*)x, thresh, (float4*)out, n4);
}

// round 5
// speedup vs baseline: 1.1432x; 1.0062x over previous
#include <cuda_runtime.h>

// StructuredPruningIF: integrate-and-fire over T=4 timesteps.
//   mem = 0.5*thre; for t in 0..3: mem += x[t]; spike = (mem>=thre)?thre:0; mem -= spike
// Pure streaming: 256MB read + 256MB write, irreducible traffic.
//
// FINAL (R5 = R1 config): flat one-shot launch, one float4 lane/thread,
// front-batched MLP=4 timestep loads, plain stores, 32 regs, block=256.
// Measured 6.49 TB/s (81% of 8TB/s spec) — at the HBM read/write-turnaround
// ceiling for a balanced 50/50 R/W stream. Ruled out by experiment:
//   R2 __ldcs/__stcs + MLP=8 (48 regs, occ 79->49%): neutral BW, worse occ.
//   R3 persistent grid-stride at exact occupancy: REGRESSED (loop-carried
//      loads behind stores -> sustained MLP drop, 6.0 TB/s).
//   R4 __stcs stores only: neutral (within run-to-run noise).

#define T_STEPS 4

__global__ __launch_bounds__(256) void if_kernel(
    const float4* __restrict__ x,
    const float* __restrict__ thresh,
    float4* __restrict__ out,
    int n4)          // spatial float4 count per timestep (== timestep stride)
{
    int i = blockIdx.x * blockDim.x + threadIdx.x;
    if (i >= n4) return;

    const float thre = __ldg(thresh);
    const long s = n4;

    // Front-batched independent loads (MLP=4): keep first in program order
    // so every CTA fills the L1tex queue immediately at launch.
    float4 x0 = x[0 * s + i];
    float4 x1 = x[1 * s + i];
    float4 x2 = x[2 * s + i];
    float4 x3 = x[3 * s + i];

    float4 xts[T_STEPS] = {x0, x1, x2, x3};
    const float half_thre = 0.5f * thre;
    float4 mem = make_float4(half_thre, half_thre, half_thre, half_thre);

#pragma unroll
    for (int t = 0; t < T_STEPS; t++) {
        float4 xt = xts[t];
        float4 spike;

        mem.x += xt.x; spike.x = (mem.x >= thre) ? thre : 0.0f; mem.x -= spike.x;
        mem.y += xt.y; spike.y = (mem.y >= thre) ? thre : 0.0f; mem.y -= spike.y;
        mem.z += xt.z; spike.z = (mem.z >= thre) ? thre : 0.0f; mem.z -= spike.z;
        mem.w += xt.w; spike.w = (mem.w >= thre) ? thre : 0.0f; mem.w -= spike.w;

        out[t * s + i] = spike;
    }
}

extern "C" void kernel_launch(void* const* d_in, const int* in_sizes, int n_in,
                              void* d_out, int out_size) {
    const float* x      = (const float*)d_in[0];   // [512,128,32,32] fp32
    const float* thresh = (const float*)d_in[1];   // [1] fp32
    float* out          = (float*)d_out;

    int total = in_sizes[0];            // 67,108,864
    int per_t = total / T_STEPS;        // 16,777,216
    int n4 = per_t / 4;                 // 4,194,304 float4 lanes

    int threads = 256;
    int blocks = (n4 + threads - 1) / threads;   // 16384
    if_kernel<<<blocks, threads>>>((const float4*)x, thresh, (float4*)out, n4);
}